// round 12
// baseline (speedup 1.0000x reference)
#include <cuda_runtime.h>
#include <cstdint>

// ---- problem constants ----
#define BSZ 8
#define SEQLEN 16
#define DIM 4096
#define NH 32
#define NKV 8
#define HD 128
#define CACHE 4096
#define M_TOT 128
#define QKV_N 6144
#define CACHE_PER_B 4194304L // 4096*8*128
#define CK_OFF 524288L
#define CV_OFF 34078720L
#define INV_SQRT_HD 0.08838834764831845f
#define QSPLIT 8
#define OSPLIT 8
#define ASPLIT 4

// ---- scratch ----
__device__ float g_qkv_part[QSPLIT][M_TOT * QKV_N];
__device__ float g_xq[64 * 64 * 128];            // [pair*64+row][d], *1/sqrt(hd)
__device__ float g_knew[BSZ * 16 * 1024];
__device__ float g_vnew[BSZ * 16 * 1024];
__device__ float g_scores[4096 * 4096];          // raw masked scores (64MB, L2-resident)
__device__ float g_pmax[4096 * 32];
__device__ float g_rowmax[4096];
__device__ float g_lpart[ASPLIT][4096];
__device__ float g_attn_part[ASPLIT][64 * 64 * 128];
__device__ float g_attn[M_TOT * 4096];
__device__ float g_out_part[OSPLIT][M_TOT * DIM];

// ---- helpers ----
__device__ __forceinline__ uint32_t f2tf(float f) {
    uint32_t u;
    asm("cvt.rna.tf32.f32 %0, %1;" : "=r"(u) : "f"(f));
    return u;
}
__device__ __forceinline__ void mma_tf32(float (&d)[4], const uint32_t (&a)[4],
                                         const uint32_t (&b)[2]) {
    asm volatile(
        "mma.sync.aligned.m16n8k8.row.col.f32.tf32.tf32.f32 "
        "{%0,%1,%2,%3}, {%4,%5,%6,%7}, {%8,%9}, {%0,%1,%2,%3};\n"
        : "+f"(d[0]), "+f"(d[1]), "+f"(d[2]), "+f"(d[3])
        : "r"(a[0]), "r"(a[1]), "r"(a[2]), "r"(a[3]), "r"(b[0]), "r"(b[1]));
}
__device__ __forceinline__ void cp16(uint32_t s, const void* g) {
    asm volatile("cp.async.cg.shared.global [%0], [%1], 16;\n" ::"r"(s), "l"(g));
}
__device__ __forceinline__ void cp_commit() { asm volatile("cp.async.commit_group;\n"); }
__device__ __forceinline__ void cp_wait0() { asm volatile("cp.async.wait_group 0;\n"); }
__device__ __forceinline__ void cp_wait1() { asm volatile("cp.async.wait_group 1;\n"); }
__device__ __forceinline__ void cp_wait2() { asm volatile("cp.async.wait_group 2;\n"); }

// ================= cache shift (side stream) =================
__global__ void shift_caches(const float4* __restrict__ ck,
                             const float4* __restrict__ cv,
                             float4* __restrict__ out) {
    long i = (long)blockIdx.x * 256 + threadIdx.x;
    const long PER = 8L * 4080 * 256;
    if (i < PER) {
        long b = i / (4080L * 256), r = i - b * (4080L * 256);
        out[CK_OFF / 4 + b * 1048576 + r] = ck[b * 1048576 + 4096 + r];
    } else if (i < 2 * PER) {
        long j = i - PER;
        long b = j / (4080L * 256), r = j - b * (4080L * 256);
        out[CV_OFF / 4 + b * 1048576 + r] = cv[b * 1048576 + 4096 + r];
    }
}

// ========== BK=32 double-buffered tf32 core: 128xN tiles, 256 threads ==========
// C += A(row,[128][K]) * B(row,[128][K])^T ; contiguous 128B/row/stage.
#define W36 36
#define TILE_W (128 * W36)          // floats per matrix per buffer
__device__ __forceinline__ void gemm_core_bk32(const float* __restrict__ A, long lda,
                                               const float* __restrict__ B, long ldb,
                                               int ktiles, float* As, float* Bs,
                                               float (&acc)[4][4][4]) {
    const int tid = threadIdx.x;
    const int lane = tid & 31, wid = tid >> 5;
    const int wm = wid >> 2, wn = wid & 3;
    const int g = lane >> 2, tig = lane & 3;
    uint32_t asS = (uint32_t)__cvta_generic_to_shared(As);
    uint32_t bsS = (uint32_t)__cvta_generic_to_shared(Bs);

    auto load_tile = [&](int t, int buf) {
        const float* Ak = A + t * 32;
        const float* Bk = B + t * 32;
#pragma unroll
        for (int i = 0; i < 4; i++) {
            int v = tid + i * 256, r = v >> 3, c4 = v & 7;
            cp16(asS + (buf * TILE_W + r * W36 + c4 * 4) * 4, Ak + (long)r * lda + c4 * 4);
        }
#pragma unroll
        for (int i = 0; i < 4; i++) {
            int v = tid + i * 256, r = v >> 3, c4 = v & 7;
            cp16(bsS + (buf * TILE_W + r * W36 + c4 * 4) * 4, Bk + (long)r * ldb + c4 * 4);
        }
        cp_commit();
    };

    load_tile(0, 0);
    for (int t = 0; t < ktiles; t++) {
        if (t + 1 < ktiles) { load_tile(t + 1, (t + 1) & 1); cp_wait1(); }
        else cp_wait0();
        __syncthreads();
        const float* Af = As + (t & 1) * TILE_W;
        const float* Bf = Bs + (t & 1) * TILE_W;
#pragma unroll
        for (int ks = 0; ks < 32; ks += 8) {
            uint32_t a[4][4], b[4][2];
#pragma unroll
            for (int mf = 0; mf < 4; mf++) {
                int m = wm * 64 + mf * 16;
                a[mf][0] = f2tf(Af[(m + g) * W36 + ks + tig]);
                a[mf][1] = f2tf(Af[(m + g + 8) * W36 + ks + tig]);
                a[mf][2] = f2tf(Af[(m + g) * W36 + ks + tig + 4]);
                a[mf][3] = f2tf(Af[(m + g + 8) * W36 + ks + tig + 4]);
            }
#pragma unroll
            for (int nf = 0; nf < 4; nf++) {
                int n = wn * 32 + nf * 8 + g;
                b[nf][0] = f2tf(Bf[n * W36 + ks + tig]);
                b[nf][1] = f2tf(Bf[n * W36 + ks + tig + 4]);
            }
#pragma unroll
            for (int mf = 0; mf < 4; mf++)
#pragma unroll
                for (int nf = 0; nf < 4; nf++) mma_tf32(acc[mf][nf], a[mf], b[nf]);
        }
        __syncthreads();
    }
}

__device__ __forceinline__ void store_acc4(float* __restrict__ C, long ldc,
                                           float (&acc)[4][4][4]) {
    const int tid = threadIdx.x;
    const int lane = tid & 31, wid = tid >> 5;
    const int wm = wid >> 2, wn = wid & 3;
    const int g = lane >> 2, tig = lane & 3;
#pragma unroll
    for (int mf = 0; mf < 4; mf++) {
        int m = wm * 64 + mf * 16 + g;
#pragma unroll
        for (int nf = 0; nf < 4; nf++) {
            int n = wn * 32 + nf * 8 + 2 * tig;
            *(float2*)(C + (long)m * ldc + n) = make_float2(acc[mf][nf][0], acc[mf][nf][1]);
            *(float2*)(C + (long)(m + 8) * ldc + n) = make_float2(acc[mf][nf][2], acc[mf][nf][3]);
        }
    }
}

#define GK_SMEM (2 * 2 * TILE_W * 4)   // 73.7 KB

// ================= QKV projection (split-K=8, BK=32) =================
__global__ void __launch_bounds__(256, 2)
qkv_gemm_t(const float* __restrict__ X, const float* __restrict__ wq,
           const float* __restrict__ wk, const float* __restrict__ wv) {
    extern __shared__ float gk_sh[];
    float* As = gk_sh;
    float* Bs = gk_sh + 2 * TILE_W;
    int n0 = blockIdx.x * 128, split = blockIdx.y;
    const float* W;
    int nl;
    if (n0 < 4096) { W = wq; nl = n0; }
    else if (n0 < 5120) { W = wk; nl = n0 - 4096; }
    else { W = wv; nl = n0 - 5120; }
    float acc[4][4][4] = {};
    gemm_core_bk32(X + split * 512, 4096, W + (long)nl * 4096 + split * 512, 4096, 16,
                   As, Bs, acc);
    store_acc4(g_qkv_part[split] + n0, QKV_N, acc);
}

// ================= RoPE + split reduce + scatter K/V =================
__global__ void rope_scatter(const float* __restrict__ freqs, float* __restrict__ out) {
    int m = blockIdx.x;
    int b = m >> 4, s = m & 15;
    long base = (long)m * QKV_N;
#pragma unroll 1
    for (int p = threadIdx.x; p < 2048; p += 256) {
        int h = p >> 6, i = p & 63;
        float re = 0.f, im = 0.f;
#pragma unroll
        for (int sp = 0; sp < QSPLIT; sp++) {
            re += g_qkv_part[sp][base + 2 * p];
            im += g_qkv_part[sp][base + 2 * p + 1];
        }
        float c = freqs[(s * 64 + i) * 2], sn = freqs[(s * 64 + i) * 2 + 1];
        long d = ((long)(b * 32 + h) * 16 + s) * 128 + 2 * i;
        g_xq[d] = (re * c - im * sn) * INV_SQRT_HD;
        g_xq[d + 1] = (re * sn + im * c) * INV_SQRT_HD;
    }
    float* cko = out + CK_OFF + (long)b * CACHE_PER_B + (long)(4080 + s) * 1024;
    float* knw = g_knew + (long)(b * 16 + s) * 1024;
#pragma unroll 1
    for (int p = threadIdx.x; p < 512; p += 256) {
        int i = p & 63;
        long o = base + 4096 + 2 * p;
        float re = 0.f, im = 0.f;
#pragma unroll
        for (int sp = 0; sp < QSPLIT; sp++) {
            re += g_qkv_part[sp][o];
            im += g_qkv_part[sp][o + 1];
        }
        float c = freqs[(s * 64 + i) * 2], sn = freqs[(s * 64 + i) * 2 + 1];
        float vr = re * c - im * sn, vi = re * sn + im * c;
        cko[2 * p] = vr; cko[2 * p + 1] = vi;
        knw[2 * p] = vr; knw[2 * p + 1] = vi;
    }
    float* cvo = out + CV_OFF + (long)b * CACHE_PER_B + (long)(4080 + s) * 1024;
    float* vnw = g_vnew + (long)(b * 16 + s) * 1024;
#pragma unroll 1
    for (int j = threadIdx.x; j < 1024; j += 256) {
        long o = base + 5120 + j;
        float v = 0.f;
#pragma unroll
        for (int sp = 0; sp < QSPLIT; sp++) v += g_qkv_part[sp][o];
        cvo[j] = v; vnw[j] = v;
    }
}

// ================= scores: 256 thr, single-shot full-K + partial row max =============
#define SC_SMEM ((64 * 132 + 128 * 132) * 4)
__global__ void scores_gemm_t(const float* __restrict__ ck, const float* __restrict__ mask) {
    extern __shared__ float sc_sh[];
    float* As = sc_sh;                 // 64 x 132
    float* Bs = sc_sh + 64 * 132;      // 128 x 132
    __shared__ float pmax_s[64][4];
    int t0 = blockIdx.x * 128, pair = blockIdx.y;
    int b = pair >> 3, kv = pair & 7;
    const int tid = threadIdx.x;
    const int lane = tid & 31, wid = tid >> 5;
    const int wm = wid >> 2, wn = wid & 3;
    const int g = lane >> 2, tig = lane & 3;
    uint32_t asS = (uint32_t)__cvta_generic_to_shared(As);
    uint32_t bsS = (uint32_t)__cvta_generic_to_shared(Bs);

#pragma unroll
    for (int i = 0; i < 8; i++) {
        int v = i * 256 + tid, r = v >> 5, c4 = v & 31;
        cp16(asS + (r * 132 + c4 * 4) * 4, g_xq + (long)pair * 8192 + r * 128 + c4 * 4);
    }
#pragma unroll
    for (int i = 0; i < 16; i++) {
        int v = i * 256 + tid, r = v >> 5, c4 = v & 31;
        int tg = t0 + r;
        const float* src =
            (tg < 4080 ? ck + (long)b * CACHE_PER_B + (long)(tg + 16) * 1024
                       : g_knew + (long)(b * 16 + tg - 4080) * 1024) + kv * 128 + c4 * 4;
        cp16(bsS + (r * 132 + c4 * 4) * 4, src);
    }
    cp_commit();
    cp_wait0();
    __syncthreads();

    float acc[2][4][4] = {};
#pragma unroll
    for (int ks = 0; ks < 128; ks += 8) {
        uint32_t a[2][4], bb[4][2];
#pragma unroll
        for (int mf = 0; mf < 2; mf++) {
            int m = wm * 32 + mf * 16;
            a[mf][0] = f2tf(As[(m + g) * 132 + ks + tig]);
            a[mf][1] = f2tf(As[(m + g + 8) * 132 + ks + tig]);
            a[mf][2] = f2tf(As[(m + g) * 132 + ks + tig + 4]);
            a[mf][3] = f2tf(As[(m + g + 8) * 132 + ks + tig + 4]);
        }
#pragma unroll
        for (int nf = 0; nf < 4; nf++) {
            int n = wn * 32 + nf * 8 + g;
            bb[nf][0] = f2tf(Bs[n * 132 + ks + tig]);
            bb[nf][1] = f2tf(Bs[n * 132 + ks + tig + 4]);
        }
#pragma unroll
        for (int mf = 0; mf < 2; mf++)
#pragma unroll
            for (int nf = 0; nf < 4; nf++) mma_tf32(acc[mf][nf], a[mf], bb[nf]);
    }

    float pm[2][2] = {{-1e30f, -1e30f}, {-1e30f, -1e30f}};
#pragma unroll
    for (int mf = 0; mf < 2; mf++) {
        int mloc = wm * 32 + mf * 16 + g;
        long r_lo = (long)pair * 64 + mloc, r_hi = r_lo + 8;
        int q_lo = mloc & 15, q_hi = (mloc + 8) & 15;
#pragma unroll
        for (int nf = 0; nf < 4; nf++) {
            int n = t0 + wn * 32 + nf * 8 + 2 * tig;
            float v0 = acc[mf][nf][0] + mask[q_lo * 4096 + n];
            float v1 = acc[mf][nf][1] + mask[q_lo * 4096 + n + 1];
            float v2 = acc[mf][nf][2] + mask[q_hi * 4096 + n];
            float v3 = acc[mf][nf][3] + mask[q_hi * 4096 + n + 1];
            *(float2*)&g_scores[r_lo * 4096 + n] = make_float2(v0, v1);
            *(float2*)&g_scores[r_hi * 4096 + n] = make_float2(v2, v3);
            pm[mf][0] = fmaxf(pm[mf][0], fmaxf(v0, v1));
            pm[mf][1] = fmaxf(pm[mf][1], fmaxf(v2, v3));
        }
    }
#pragma unroll
    for (int mf = 0; mf < 2; mf++)
#pragma unroll
        for (int h = 0; h < 2; h++) {
            float m = pm[mf][h];
            m = fmaxf(m, __shfl_xor_sync(0xffffffffu, m, 1));
            m = fmaxf(m, __shfl_xor_sync(0xffffffffu, m, 2));
            if (tig == 0) pmax_s[wm * 32 + mf * 16 + g + h * 8][wn] = m;
        }
    __syncthreads();
    if (tid < 64) {
        float m = fmaxf(fmaxf(pmax_s[tid][0], pmax_s[tid][1]),
                        fmaxf(pmax_s[tid][2], pmax_s[tid][3]));
        g_pmax[(pair * 64 + tid) * 32 + blockIdx.x] = m;
    }
}

// ================= row max reduce =================
__global__ void rowmax_reduce() {
    int row = blockIdx.x * 256 + threadIdx.x;
    float m = -1e30f;
#pragma unroll
    for (int j = 0; j < 32; j++) m = fmaxf(m, g_pmax[row * 32 + j]);
    g_rowmax[row] = m;
}

// ================= attnv: 256 thr, exp fused at A-stage, BK=64, split-K=4 ============
#define AT_A_W (64 * 68)
#define AT_V_W (64 * 136)
#define AT_SMEM ((AT_A_W * 2 + 2 * AT_V_W) * 4)
__global__ void attnv_gemm_t(const float* __restrict__ cv) {
    extern __shared__ float at_sh[];
    float* As2 = at_sh;
    uint32_t* Es = (uint32_t*)(at_sh + AT_A_W);
    float* Vs = at_sh + 2 * AT_A_W;
    __shared__ float mrow_s[64];
    __shared__ float lrow_s[64];

    int pair = blockIdx.x, split = blockIdx.y;
    int b = pair >> 3, kvv = pair & 7;
    const int tid = threadIdx.x;
    const int lane = tid & 31, wid = tid >> 5;
    const int wm = wid >> 2, wn = wid & 3;
    const int g = lane >> 2, tig = lane & 3;
    int k0 = split * 1024;
    const float* A = g_scores + (long)pair * 64 * 4096 + k0;
    uint32_t asS = (uint32_t)__cvta_generic_to_shared(As2);
    uint32_t vsS = (uint32_t)__cvta_generic_to_shared(Vs);

    if (tid < 64) {
        mrow_s[tid] = g_rowmax[pair * 64 + tid];
        lrow_s[tid] = 0.f;
    }

    auto loadA = [&](int t) {
#pragma unroll
        for (int i = 0; i < 4; i++) {
            int v = i * 256 + tid, r = v >> 4, c4 = v & 15;
            cp16(asS + (r * 68 + c4 * 4) * 4, A + (long)r * 4096 + t * 64 + c4 * 4);
        }
        cp_commit();
    };
    auto loadV = [&](int t, int buf) {
#pragma unroll
        for (int i = 0; i < 8; i++) {
            int v = i * 256 + tid, r = v >> 5, c4 = v & 31;
            int tg = k0 + t * 64 + r;
            const float* src =
                (tg < 4080 ? cv + (long)b * CACHE_PER_B + (long)(tg + 16) * 1024
                           : g_vnew + (long)(b * 16 + tg - 4080) * 1024) + kvv * 128 + c4 * 4;
            cp16(vsS + (buf * AT_V_W + r * 136 + c4 * 4) * 4, src);
        }
        cp_commit();
    };

    loadA(0);
    loadV(0, 0);

    float acc[2][4][4] = {};
    for (int t = 0; t < 16; t++) {
        cp_wait1();
        __syncthreads();
#pragma unroll
        for (int i = 0; i < 16; i++) {
            int v = i * 256 + tid, r = v >> 6, c = v & 63;
            float e = __expf(As2[r * 68 + c] - mrow_s[r]);
            Es[r * 68 + c] = f2tf(e);
            float s = e;
#pragma unroll
            for (int off = 16; off; off >>= 1) s += __shfl_xor_sync(0xffffffffu, s, off);
            if (lane == 0) atomicAdd(&lrow_s[r], s);
        }
        __syncthreads();
        if (t + 1 < 16) {
            loadA(t + 1);
            loadV(t + 1, (t + 1) & 1);
            cp_wait2();
        } else {
            cp_wait0();
        }
        __syncthreads();
        const float* Vf = Vs + (t & 1) * AT_V_W;
#pragma unroll
        for (int ks = 0; ks < 64; ks += 8) {
            uint32_t a[2][4], bb[4][2];
#pragma unroll
            for (int mf = 0; mf < 2; mf++) {
                int m = wm * 32 + mf * 16;
                a[mf][0] = Es[(m + g) * 68 + ks + tig];
                a[mf][1] = Es[(m + g + 8) * 68 + ks + tig];
                a[mf][2] = Es[(m + g) * 68 + ks + tig + 4];
                a[mf][3] = Es[(m + g + 8) * 68 + ks + tig + 4];
            }
#pragma unroll
            for (int nf = 0; nf < 4; nf++) {
                int n = wn * 32 + nf * 8 + g;
                bb[nf][0] = f2tf(Vf[(ks + tig) * 136 + n]);
                bb[nf][1] = f2tf(Vf[(ks + tig + 4) * 136 + n]);
            }
#pragma unroll
            for (int mf = 0; mf < 2; mf++)
#pragma unroll
                for (int nf = 0; nf < 4; nf++) mma_tf32(acc[mf][nf], a[mf], bb[nf]);
        }
    }
    {
        float* C = g_attn_part[split] + (long)pair * 64 * 128;
#pragma unroll
        for (int mf = 0; mf < 2; mf++) {
            int m = wm * 32 + mf * 16 + g;
#pragma unroll
            for (int nf = 0; nf < 4; nf++) {
                int n = wn * 32 + nf * 8 + 2 * tig;
                *(float2*)(C + (long)m * 128 + n) = make_float2(acc[mf][nf][0], acc[mf][nf][1]);
                *(float2*)(C + (long)(m + 8) * 128 + n) =
                    make_float2(acc[mf][nf][2], acc[mf][nf][3]);
            }
        }
    }
    __syncthreads();
    if (tid < 64) g_lpart[split][pair * 64 + tid] = lrow_s[tid];
}

// ================= attnv reduce: sum splits, divide by l =================
__global__ void attnv_reduce() {
    long idx = (long)blockIdx.x * 256 + threadIdx.x;  // float4 index
    long o = idx * 4;
    int pair = (int)(o >> 13), r = (int)((o >> 7) & 63), d = (int)(o & 127);
    float l = g_lpart[0][pair * 64 + r] + g_lpart[1][pair * 64 + r] +
              g_lpart[2][pair * 64 + r] + g_lpart[3][pair * 64 + r];
    float inv = 1.0f / l;
    float4 p0 = ((const float4*)g_attn_part[0])[idx];
    float4 p1 = ((const float4*)g_attn_part[1])[idx];
    float4 p2 = ((const float4*)g_attn_part[2])[idx];
    float4 p3 = ((const float4*)g_attn_part[3])[idx];
    float4 s = make_float4((p0.x + p1.x + p2.x + p3.x) * inv, (p0.y + p1.y + p2.y + p3.y) * inv,
                           (p0.z + p1.z + p2.z + p3.z) * inv, (p0.w + p1.w + p2.w + p3.w) * inv);
    int bb = pair >> 3, kv = pair & 7, hp = r >> 4, q = r & 15;
    *(float4*)(g_attn + ((long)(bb * 16 + q) * 4096 + (kv * 4 + hp) * 128 + d)) = s;
}

// ================= out = attn @ wo^T (split-K=8, BK=32) =================
__global__ void __launch_bounds__(256, 2)
out_gemm_t(const float* __restrict__ wo) {
    extern __shared__ float gk_sh2[];
    float* As = gk_sh2;
    float* Bs = gk_sh2 + 2 * TILE_W;
    int n0 = blockIdx.x * 128, split = blockIdx.y;
    float acc[4][4][4] = {};
    gemm_core_bk32(g_attn + split * 512, 4096, wo + (long)n0 * 4096 + split * 512, 4096, 16,
                   As, Bs, acc);
    store_acc4(g_out_part[split] + n0, 4096, acc);
}

__global__ void out_reduce(float* __restrict__ out) {
    long idx = (long)blockIdx.x * 256 + threadIdx.x;
    float4 s = make_float4(0.f, 0.f, 0.f, 0.f);
#pragma unroll
    for (int sp = 0; sp < OSPLIT; sp++) {
        float4 p = ((const float4*)g_out_part[sp])[idx];
        s.x += p.x; s.y += p.y; s.z += p.z; s.w += p.w;
    }
    ((float4*)out)[idx] = s;
}

// ================= launch =================
extern "C" void kernel_launch(void* const* d_in, const int* in_sizes, int n_in,
                              void* d_out, int out_size) {
    const float* x     = (const float*)d_in[0];
    const float* mask  = (const float*)d_in[1];
    const float* freqs = (const float*)d_in[2];
    const float* ck    = (const float*)d_in[3];
    const float* cv    = (const float*)d_in[4];
    const float* wq    = (const float*)d_in[5];
    const float* wk    = (const float*)d_in[6];
    const float* wv    = (const float*)d_in[7];
    const float* wo    = (const float*)d_in[8];
    float* out = (float*)d_out;

    static cudaStream_t s_copy = nullptr;
    static cudaEvent_t ev_fork = nullptr, ev_join = nullptr;
    if (!s_copy) {
        cudaStreamCreateWithFlags(&s_copy, cudaStreamNonBlocking);
        cudaEventCreateWithFlags(&ev_fork, cudaEventDisableTiming);
        cudaEventCreateWithFlags(&ev_join, cudaEventDisableTiming);
        cudaFuncSetAttribute(scores_gemm_t, cudaFuncAttributeMaxDynamicSharedMemorySize,
                             SC_SMEM);
        cudaFuncSetAttribute(attnv_gemm_t, cudaFuncAttributeMaxDynamicSharedMemorySize,
                             AT_SMEM);
        cudaFuncSetAttribute(qkv_gemm_t, cudaFuncAttributeMaxDynamicSharedMemorySize,
                             GK_SMEM);
        cudaFuncSetAttribute(out_gemm_t, cudaFuncAttributeMaxDynamicSharedMemorySize,
                             GK_SMEM);
    }

    cudaEventRecord(ev_fork, 0);
    cudaStreamWaitEvent(s_copy, ev_fork, 0);
    shift_caches<<<65280, 256, 0, s_copy>>>((const float4*)ck, (const float4*)cv,
                                            (float4*)out);
    cudaEventRecord(ev_join, s_copy);

    qkv_gemm_t<<<dim3(48, QSPLIT), 256, GK_SMEM>>>(x, wq, wk, wv);
    rope_scatter<<<128, 256>>>(freqs, out);
    scores_gemm_t<<<dim3(32, 64), 256, SC_SMEM>>>(ck, mask);
    rowmax_reduce<<<16, 256>>>();
    attnv_gemm_t<<<dim3(64, ASPLIT), 256, AT_SMEM>>>(cv);
    attnv_reduce<<<512, 256>>>();
    out_gemm_t<<<dim3(32, OSPLIT), 256, GK_SMEM>>>(wo);
    out_reduce<<<512, 256>>>(out);

    cudaStreamWaitEvent(0, ev_join, 0);
}

// round 13
// speedup vs baseline: 1.5357x; 1.5357x over previous
#include <cuda_runtime.h>
#include <cstdint>

// ---- problem constants ----
#define BSZ 8
#define SEQLEN 16
#define DIM 4096
#define NH 32
#define NKV 8
#define HD 128
#define CACHE 4096
#define M_TOT 128
#define QKV_N 6144
#define CACHE_PER_B 4194304L // 4096*8*128
#define CK_OFF 524288L
#define CV_OFF 34078720L
#define INV_SQRT_HD 0.08838834764831845f

// ---- scratch ----
__device__ float g_qkv_part[4][M_TOT * QKV_N];
__device__ float g_xq[64 * 64 * 128];            // [pair*64+row][d], pre-scaled 1/sqrt(hd)
__device__ float g_knew[BSZ * 16 * 1024];        // [b*16+s][kv*128+d] rope'd new K
__device__ float g_vnew[BSZ * 16 * 1024];        // new V
__device__ float g_scores[4096 * 4096];          // [pair*64+r][t]  (64MB, L2-resident)
__device__ float g_attn_part[4][64 * 64 * 128];
__device__ float g_attn[M_TOT * 4096];
__device__ float g_out_part[4][M_TOT * DIM];

// ---- helpers ----
__device__ __forceinline__ uint32_t f2tf(float f) {
    uint32_t u;
    asm("cvt.rna.tf32.f32 %0, %1;" : "=r"(u) : "f"(f));
    return u;
}
__device__ __forceinline__ void mma_tf32(float (&d)[4], const uint32_t (&a)[4],
                                         const uint32_t (&b)[2]) {
    asm volatile(
        "mma.sync.aligned.m16n8k8.row.col.f32.tf32.tf32.f32 "
        "{%0,%1,%2,%3}, {%4,%5,%6,%7}, {%8,%9}, {%0,%1,%2,%3};\n"
        : "+f"(d[0]), "+f"(d[1]), "+f"(d[2]), "+f"(d[3])
        : "r"(a[0]), "r"(a[1]), "r"(a[2]), "r"(a[3]), "r"(b[0]), "r"(b[1]));
}
__device__ __forceinline__ void cp16(uint32_t s, const void* g) {
    asm volatile("cp.async.cg.shared.global [%0], [%1], 16;\n" ::"r"(s), "l"(g));
}
__device__ __forceinline__ void cp_commit() { asm volatile("cp.async.commit_group;\n"); }
__device__ __forceinline__ void cp_wait1() { asm volatile("cp.async.wait_group 1;\n"); }
__device__ __forceinline__ void cp_wait0() { asm volatile("cp.async.wait_group 0;\n"); }
__device__ __forceinline__ void cp_wait2() { asm volatile("cp.async.wait_group 2;\n"); }

// ================= cache shift (runs on side stream, no consumer) =================
__global__ void shift_caches(const float4* __restrict__ ck,
                             const float4* __restrict__ cv,
                             float4* __restrict__ out) {
    long i = (long)blockIdx.x * 256 + threadIdx.x;
    const long PER = 8L * 4080 * 256;
    if (i < PER) {
        long b = i / (4080L * 256), r = i - b * (4080L * 256);
        out[CK_OFF / 4 + b * 1048576 + r] = ck[b * 1048576 + 4096 + r];
    } else if (i < 2 * PER) {
        long j = i - PER;
        long b = j / (4080L * 256), r = j - b * (4080L * 256);
        out[CV_OFF / 4 + b * 1048576 + r] = cv[b * 1048576 + 4096 + r];
    }
}

// ========== async double-buffered tf32 core: C += A(row,[M][K]) * B(row,[N][K])^T =====
template <int MF>
__device__ __forceinline__ void gemm_core_async(const float* __restrict__ A, long lda,
                                                const float* __restrict__ B, long ldb,
                                                int ktiles, float* As, float* Bs,
                                                float (&acc)[MF][4][4]) {
    const int tid = threadIdx.x;
    const int lane = tid & 31, wid = tid >> 5;
    const int wm = wid >> 2, wn = wid & 3;
    const int g = lane >> 2, tig = lane & 3;
    const int ASZW = MF * 32 * 20, BSZW = 128 * 20;
    uint32_t asS = (uint32_t)__cvta_generic_to_shared(As);
    uint32_t bsS = (uint32_t)__cvta_generic_to_shared(Bs);

    auto load_tile = [&](int t, int buf) {
        const float* Ak = A + t * 16;
        const float* Bk = B + t * 16;
#pragma unroll
        for (int i = 0; i < MF / 2; i++) {
            int v = tid + i * 256, r = v >> 2, c4 = v & 3;
            cp16(asS + (buf * ASZW + r * 20 + c4 * 4) * 4, Ak + (long)r * lda + c4 * 4);
        }
#pragma unroll
        for (int i = 0; i < 2; i++) {
            int v = tid + i * 256, r = v >> 2, c4 = v & 3;
            cp16(bsS + (buf * BSZW + r * 20 + c4 * 4) * 4, Bk + (long)r * ldb + c4 * 4);
        }
        cp_commit();
    };

    load_tile(0, 0);
    for (int t = 0; t < ktiles; t++) {
        if (t + 1 < ktiles) { load_tile(t + 1, (t + 1) & 1); cp_wait1(); }
        else cp_wait0();
        __syncthreads();
        const float* Af = As + (t & 1) * ASZW;
        const float* Bf = Bs + (t & 1) * BSZW;
#pragma unroll
        for (int ks = 0; ks < 16; ks += 8) {
            uint32_t a[MF][4], b[4][2];
#pragma unroll
            for (int mf = 0; mf < MF; mf++) {
                int m = wm * (MF * 16) + mf * 16;
                a[mf][0] = f2tf(Af[(m + g) * 20 + ks + tig]);
                a[mf][1] = f2tf(Af[(m + g + 8) * 20 + ks + tig]);
                a[mf][2] = f2tf(Af[(m + g) * 20 + ks + tig + 4]);
                a[mf][3] = f2tf(Af[(m + g + 8) * 20 + ks + tig + 4]);
            }
#pragma unroll
            for (int nf = 0; nf < 4; nf++) {
                int n = wn * 32 + nf * 8 + g;
                b[nf][0] = f2tf(Bf[n * 20 + ks + tig]);
                b[nf][1] = f2tf(Bf[n * 20 + ks + tig + 4]);
            }
#pragma unroll
            for (int mf = 0; mf < MF; mf++)
#pragma unroll
                for (int nf = 0; nf < 4; nf++) mma_tf32(acc[mf][nf], a[mf], b[nf]);
        }
        __syncthreads();
    }
}

template <int MF>
__device__ __forceinline__ void store_acc(float* __restrict__ C, long ldc,
                                          float (&acc)[MF][4][4]) {
    const int tid = threadIdx.x;
    const int lane = tid & 31, wid = tid >> 5;
    const int wm = wid >> 2, wn = wid & 3;
    const int g = lane >> 2, tig = lane & 3;
#pragma unroll
    for (int mf = 0; mf < MF; mf++) {
        int m = wm * (MF * 16) + mf * 16 + g;
#pragma unroll
        for (int nf = 0; nf < 4; nf++) {
            int n = wn * 32 + nf * 8 + 2 * tig;
            *(float2*)(C + (long)m * ldc + n) = make_float2(acc[mf][nf][0], acc[mf][nf][1]);
            *(float2*)(C + (long)(m + 8) * ldc + n) = make_float2(acc[mf][nf][2], acc[mf][nf][3]);
        }
    }
}

// ================= QKV projection (split-K=4) =================
__global__ void qkv_gemm_t(const float* __restrict__ X, const float* __restrict__ wq,
                           const float* __restrict__ wk, const float* __restrict__ wv) {
    __shared__ float As[2 * 128 * 20], Bs[2 * 128 * 20];
    int n0 = blockIdx.x * 128, split = blockIdx.y;
    const float* W;
    int nl;
    if (n0 < 4096) { W = wq; nl = n0; }
    else if (n0 < 5120) { W = wk; nl = n0 - 4096; }
    else { W = wv; nl = n0 - 5120; }
    float acc[4][4][4] = {};
    gemm_core_async<4>(X + split * 1024, 4096, W + (long)nl * 4096 + split * 1024, 4096, 64,
                       As, Bs, acc);
    store_acc<4>(g_qkv_part[split] + n0, QKV_N, acc);
}

// ================= RoPE + split reduce + scatter K/V (scratch + out tails) ===========
__global__ void rope_scatter(const float* __restrict__ freqs, float* __restrict__ out) {
    int m = blockIdx.x;
    int b = m >> 4, s = m & 15;
    long base = (long)m * QKV_N;
#pragma unroll 1
    for (int p = threadIdx.x; p < 2048; p += 256) {
        int h = p >> 6, i = p & 63;
        float re = g_qkv_part[0][base + 2 * p] + g_qkv_part[1][base + 2 * p] +
                   g_qkv_part[2][base + 2 * p] + g_qkv_part[3][base + 2 * p];
        float im = g_qkv_part[0][base + 2 * p + 1] + g_qkv_part[1][base + 2 * p + 1] +
                   g_qkv_part[2][base + 2 * p + 1] + g_qkv_part[3][base + 2 * p + 1];
        float c = freqs[(s * 64 + i) * 2], sn = freqs[(s * 64 + i) * 2 + 1];
        long d = ((long)(b * 32 + h) * 16 + s) * 128 + 2 * i;
        g_xq[d] = (re * c - im * sn) * INV_SQRT_HD;
        g_xq[d + 1] = (re * sn + im * c) * INV_SQRT_HD;
    }
    float* cko = out + CK_OFF + (long)b * CACHE_PER_B + (long)(4080 + s) * 1024;
    float* knw = g_knew + (long)(b * 16 + s) * 1024;
#pragma unroll 1
    for (int p = threadIdx.x; p < 512; p += 256) {
        int i = p & 63;
        long o = base + 4096 + 2 * p;
        float re = g_qkv_part[0][o] + g_qkv_part[1][o] + g_qkv_part[2][o] + g_qkv_part[3][o];
        float im = g_qkv_part[0][o + 1] + g_qkv_part[1][o + 1] + g_qkv_part[2][o + 1] +
                   g_qkv_part[3][o + 1];
        float c = freqs[(s * 64 + i) * 2], sn = freqs[(s * 64 + i) * 2 + 1];
        float vr = re * c - im * sn, vi = re * sn + im * c;
        cko[2 * p] = vr; cko[2 * p + 1] = vi;
        knw[2 * p] = vr; knw[2 * p + 1] = vi;
    }
    float* cvo = out + CV_OFF + (long)b * CACHE_PER_B + (long)(4080 + s) * 1024;
    float* vnw = g_vnew + (long)(b * 16 + s) * 1024;
#pragma unroll 1
    for (int j = threadIdx.x; j < 1024; j += 256) {
        long o = base + 5120 + j;
        float v = g_qkv_part[0][o] + g_qkv_part[1][o] + g_qkv_part[2][o] + g_qkv_part[3][o];
        cvo[j] = v; vnw[j] = v;
    }
}

// ================= scores = q @ K^T + mask  (reads ORIGINAL cache at t+16) ==========
__global__ void scores_gemm_t(const float* __restrict__ ck, const float* __restrict__ mask) {
    __shared__ float As[2 * 64 * 20], Bs[2 * 128 * 20];
    int t0 = blockIdx.x * 128, pair = blockIdx.y;
    int b = pair >> 3, kv = pair & 7;
    const int tid = threadIdx.x;
    const int lane = tid & 31, wid = tid >> 5;
    const int wm = wid >> 2, wn = wid & 3;
    const int g = lane >> 2, tig = lane & 3;
    const int ASZW = 64 * 20, BSZW = 128 * 20;
    uint32_t asS = (uint32_t)__cvta_generic_to_shared(As);
    uint32_t bsS = (uint32_t)__cvta_generic_to_shared(Bs);

    const float* srcA;
    { int r = tid >> 2, c4 = tid & 3;
      srcA = g_xq + (long)pair * 8192 + r * 128 + c4 * 4; }
    const float* srcB[2];
#pragma unroll
    for (int i = 0; i < 2; i++) {
        int v = tid + i * 256, r = v >> 2, c4 = v & 3;
        int tg = t0 + r;
        srcB[i] = (tg < 4080 ? ck + (long)b * CACHE_PER_B + (long)(tg + 16) * 1024
                             : g_knew + (long)(b * 16 + tg - 4080) * 1024) + kv * 128 + c4 * 4;
    }
    auto load_tile = [&](int t, int buf) {
        { int r = tid >> 2, c4 = tid & 3;
          cp16(asS + (buf * ASZW + r * 20 + c4 * 4) * 4, srcA + t * 16); }
#pragma unroll
        for (int i = 0; i < 2; i++) {
            int v = tid + i * 256, r = v >> 2, c4 = v & 3;
            cp16(bsS + (buf * BSZW + r * 20 + c4 * 4) * 4, srcB[i] + t * 16);
        }
        cp_commit();
    };

    float acc[2][4][4] = {};
    load_tile(0, 0);
    for (int t = 0; t < 8; t++) {
        if (t + 1 < 8) { load_tile(t + 1, (t + 1) & 1); cp_wait1(); }
        else cp_wait0();
        __syncthreads();
        const float* Af = As + (t & 1) * ASZW;
        const float* Bf = Bs + (t & 1) * BSZW;
#pragma unroll
        for (int ks = 0; ks < 16; ks += 8) {
            uint32_t a[2][4], bb[4][2];
#pragma unroll
            for (int mf = 0; mf < 2; mf++) {
                int m = wm * 32 + mf * 16;
                a[mf][0] = f2tf(Af[(m + g) * 20 + ks + tig]);
                a[mf][1] = f2tf(Af[(m + g + 8) * 20 + ks + tig]);
                a[mf][2] = f2tf(Af[(m + g) * 20 + ks + tig + 4]);
                a[mf][3] = f2tf(Af[(m + g + 8) * 20 + ks + tig + 4]);
            }
#pragma unroll
            for (int nf = 0; nf < 4; nf++) {
                int n = wn * 32 + nf * 8 + g;
                bb[nf][0] = f2tf(Bf[n * 20 + ks + tig]);
                bb[nf][1] = f2tf(Bf[n * 20 + ks + tig + 4]);
            }
#pragma unroll
            for (int mf = 0; mf < 2; mf++)
#pragma unroll
                for (int nf = 0; nf < 4; nf++) mma_tf32(acc[mf][nf], a[mf], bb[nf]);
        }
        __syncthreads();
    }
#pragma unroll
    for (int mf = 0; mf < 2; mf++) {
        int m = wm * 32 + mf * 16 + g;
#pragma unroll
        for (int nf = 0; nf < 4; nf++) {
            int n = t0 + wn * 32 + nf * 8 + 2 * tig;
            {
                long row = (long)pair * 64 + m; int q = m & 15;
                g_scores[row * 4096 + n]     = acc[mf][nf][0] + mask[q * 4096 + n];
                g_scores[row * 4096 + n + 1] = acc[mf][nf][1] + mask[q * 4096 + n + 1];
            }
            {
                long row = (long)pair * 64 + m + 8; int q = (m + 8) & 15;
                g_scores[row * 4096 + n]     = acc[mf][nf][2] + mask[q * 4096 + n];
                g_scores[row * 4096 + n + 1] = acc[mf][nf][3] + mask[q * 4096 + n + 1];
            }
        }
    }
}

// ================= row softmax over 4096 (float4 vectorized) =================
__global__ void softmax_k() {
    float4* row = (float4*)(g_scores + (long)blockIdx.x * 4096);  // 1024 float4
    int tid = threadIdx.x;
    float4 v[4];
    float mx = -1e30f;
#pragma unroll
    for (int j = 0; j < 4; j++) {
        v[j] = row[tid + j * 256];
        mx = fmaxf(mx, fmaxf(fmaxf(v[j].x, v[j].y), fmaxf(v[j].z, v[j].w)));
    }
    __shared__ float red[8];
#pragma unroll
    for (int o = 16; o; o >>= 1) mx = fmaxf(mx, __shfl_xor_sync(0xffffffffu, mx, o));
    if ((tid & 31) == 0) red[tid >> 5] = mx;
    __syncthreads();
    mx = red[0];
#pragma unroll
    for (int i = 1; i < 8; i++) mx = fmaxf(mx, red[i]);
    float s = 0.f;
#pragma unroll
    for (int j = 0; j < 4; j++) {
        v[j].x = __expf(v[j].x - mx); v[j].y = __expf(v[j].y - mx);
        v[j].z = __expf(v[j].z - mx); v[j].w = __expf(v[j].w - mx);
        s += v[j].x + v[j].y + v[j].z + v[j].w;
    }
#pragma unroll
    for (int o = 16; o; o >>= 1) s += __shfl_xor_sync(0xffffffffu, s, o);
    __syncthreads();
    if ((tid & 31) == 0) red[tid >> 5] = s;
    __syncthreads();
    float tot = 0.f;
#pragma unroll
    for (int i = 0; i < 8; i++) tot += red[i];
    float inv = 1.0f / tot;
#pragma unroll
    for (int j = 0; j < 4; j++) {
        v[j].x *= inv; v[j].y *= inv; v[j].z *= inv; v[j].w *= inv;
        row[tid + j * 256] = v[j];
    }
}

// ================= attn = probs @ V  (split-K=4; V from original cache at t+16) =====
__global__ void attnv_gemm_t(const float* __restrict__ cv) {
    __shared__ float As[2 * 64 * 20], Vs[2 * 16 * 136];
    int pair = blockIdx.x, split = blockIdx.y;
    int b = pair >> 3, kvv = pair & 7;
    const int tid = threadIdx.x;
    const int lane = tid & 31, wid = tid >> 5;
    const int wm = wid >> 2, wn = wid & 3;
    const int g = lane >> 2, tig = lane & 3;
    const int ASZW = 64 * 20, VSZW = 16 * 136;
    uint32_t asS = (uint32_t)__cvta_generic_to_shared(As);
    uint32_t vsS = (uint32_t)__cvta_generic_to_shared(Vs);
    const float* A = g_scores + (long)pair * 64 * 4096 + split * 1024;
    int k0 = split * 1024;

    auto load_tile = [&](int t, int buf) {
        { int r = tid >> 2, c4 = tid & 3;
          cp16(asS + (buf * ASZW + r * 20 + c4 * 4) * 4, A + (long)r * 4096 + t * 16 + c4 * 4); }
#pragma unroll
        for (int i = 0; i < 2; i++) {
            int v = tid + i * 256;
            int kk = v >> 5, n4 = v & 31;
            int tg = k0 + t * 16 + kk;
            const float* src =
                (tg < 4080 ? cv + (long)b * CACHE_PER_B + (long)(tg + 16) * 1024
                           : g_vnew + (long)(b * 16 + tg - 4080) * 1024) + kvv * 128 + n4 * 4;
            cp16(vsS + (buf * VSZW + kk * 136 + n4 * 4) * 4, src);
        }
        cp_commit();
    };

    float acc[2][4][4] = {};
    load_tile(0, 0);
    for (int t = 0; t < 64; t++) {
        if (t + 1 < 64) { load_tile(t + 1, (t + 1) & 1); cp_wait1(); }
        else cp_wait0();
        __syncthreads();
        const float* Af = As + (t & 1) * ASZW;
        const float* Vf = Vs + (t & 1) * VSZW;
#pragma unroll
        for (int ks = 0; ks < 16; ks += 8) {
            uint32_t a[2][4], bb[4][2];
#pragma unroll
            for (int mf = 0; mf < 2; mf++) {
                int m = wm * 32 + mf * 16;
                a[mf][0] = f2tf(Af[(m + g) * 20 + ks + tig]);
                a[mf][1] = f2tf(Af[(m + g + 8) * 20 + ks + tig]);
                a[mf][2] = f2tf(Af[(m + g) * 20 + ks + tig + 4]);
                a[mf][3] = f2tf(Af[(m + g + 8) * 20 + ks + tig + 4]);
            }
#pragma unroll
            for (int nf = 0; nf < 4; nf++) {
                int n = wn * 32 + nf * 8 + g;
                bb[nf][0] = f2tf(Vf[(ks + tig) * 136 + n]);
                bb[nf][1] = f2tf(Vf[(ks + tig + 4) * 136 + n]);
            }
#pragma unroll
            for (int mf = 0; mf < 2; mf++)
#pragma unroll
                for (int nf = 0; nf < 4; nf++) mma_tf32(acc[mf][nf], a[mf], bb[nf]);
        }
        __syncthreads();
    }
    store_acc<2>(g_attn_part[split] + (long)pair * 64 * 128, 128, acc);
}

__global__ void attnv_reduce() {
    long idx = (long)blockIdx.x * 256 + threadIdx.x;  // float4 index
    long o = idx * 4;
    float4 p0 = ((const float4*)g_attn_part[0])[idx];
    float4 p1 = ((const float4*)g_attn_part[1])[idx];
    float4 p2 = ((const float4*)g_attn_part[2])[idx];
    float4 p3 = ((const float4*)g_attn_part[3])[idx];
    float4 s = make_float4(p0.x + p1.x + p2.x + p3.x, p0.y + p1.y + p2.y + p3.y,
                           p0.z + p1.z + p2.z + p3.z, p0.w + p1.w + p2.w + p3.w);
    int pair = (int)(o >> 13), r = (int)((o >> 7) & 63), d = (int)(o & 127);
    int b = pair >> 3, kv = pair & 7, hp = r >> 4, q = r & 15;
    *(float4*)(g_attn + ((long)(b * 16 + q) * 4096 + (kv * 4 + hp) * 128 + d)) = s;
}

// ================= out = attn @ wo^T (split-K=4) =================
__global__ void out_gemm_t(const float* __restrict__ wo) {
    __shared__ float As[2 * 128 * 20], Bs[2 * 128 * 20];
    int n0 = blockIdx.x * 128, split = blockIdx.y;
    float acc[4][4][4] = {};
    gemm_core_async<4>(g_attn + split * 1024, 4096, wo + (long)n0 * 4096 + split * 1024, 4096,
                       64, As, Bs, acc);
    store_acc<4>(g_out_part[split] + n0, 4096, acc);
}

__global__ void out_reduce(float* __restrict__ out) {
    long idx = (long)blockIdx.x * 256 + threadIdx.x;
    float4 p0 = ((const float4*)g_out_part[0])[idx];
    float4 p1 = ((const float4*)g_out_part[1])[idx];
    float4 p2 = ((const float4*)g_out_part[2])[idx];
    float4 p3 = ((const float4*)g_out_part[3])[idx];
    ((float4*)out)[idx] = make_float4(p0.x + p1.x + p2.x + p3.x, p0.y + p1.y + p2.y + p3.y,
                                      p0.z + p1.z + p2.z + p3.z, p0.w + p1.w + p2.w + p3.w);
}

// ================= launch =================
extern "C" void kernel_launch(void* const* d_in, const int* in_sizes, int n_in,
                              void* d_out, int out_size) {
    const float* x     = (const float*)d_in[0];
    const float* mask  = (const float*)d_in[1];
    const float* freqs = (const float*)d_in[2];
    const float* ck    = (const float*)d_in[3];
    const float* cv    = (const float*)d_in[4];
    const float* wq    = (const float*)d_in[5];
    const float* wk    = (const float*)d_in[6];
    const float* wv    = (const float*)d_in[7];
    const float* wo    = (const float*)d_in[8];
    float* out = (float*)d_out;

    // one-time side-stream setup (host objects only; no device memory)
    static cudaStream_t s_copy = nullptr;
    static cudaEvent_t ev_fork = nullptr, ev_join = nullptr;
    if (!s_copy) {
        cudaStreamCreateWithFlags(&s_copy, cudaStreamNonBlocking);
        cudaEventCreateWithFlags(&ev_fork, cudaEventDisableTiming);
        cudaEventCreateWithFlags(&ev_join, cudaEventDisableTiming);
    }

    // fork: cache shift overlaps all compute (nothing downstream reads shifted copy)
    cudaEventRecord(ev_fork, 0);
    cudaStreamWaitEvent(s_copy, ev_fork, 0);
    shift_caches<<<65280, 256, 0, s_copy>>>((const float4*)ck, (const float4*)cv,
                                            (float4*)out);
    cudaEventRecord(ev_join, s_copy);

    // compute chain on main stream, reading ORIGINAL caches
    qkv_gemm_t<<<dim3(48, 4), 256>>>(x, wq, wk, wv);
    rope_scatter<<<128, 256>>>(freqs, out);
    scores_gemm_t<<<dim3(32, 64), 256>>>(ck, mask);
    softmax_k<<<4096, 256>>>();
    attnv_gemm_t<<<dim3(64, 4), 256>>>(cv);
    attnv_reduce<<<512, 256>>>();
    out_gemm_t<<<dim3(32, 4), 256>>>(wo);
    out_reduce<<<512, 256>>>(out);

    // join: shift must complete before harness observes d_out
    cudaStreamWaitEvent(0, ev_join, 0);
}

// round 14
// speedup vs baseline: 1.6226x; 1.0566x over previous
#include <cuda_runtime.h>
#include <cstdint>

// ---- problem constants ----
#define BSZ 8
#define SEQLEN 16
#define DIM 4096
#define NH 32
#define NKV 8
#define HD 128
#define CACHE 4096
#define M_TOT 128
#define QKV_N 6144
#define CACHE_PER_B 4194304L // 4096*8*128
#define CK_OFF 524288L
#define CV_OFF 34078720L
#define INV_SQRT_HD 0.08838834764831845f
#define QSPLIT 8
#define OSPLIT 8

// ---- scratch ----
__device__ float g_qkv_part[QSPLIT][M_TOT * QKV_N];
__device__ float g_xq[64 * 64 * 128];            // [pair*64+row][d], pre-scaled 1/sqrt(hd)
__device__ float g_knew[BSZ * 16 * 1024];        // [b*16+s][kv*128+d] rope'd new K
__device__ float g_vnew[BSZ * 16 * 1024];        // new V
__device__ float g_scores[4096 * 4096];          // [pair*64+r][t]  (64MB, L2-resident)
__device__ float g_attn_part[4][64 * 64 * 128];
__device__ float g_attn[M_TOT * 4096];
__device__ float g_out_part[OSPLIT][M_TOT * DIM];

// ---- helpers ----
__device__ __forceinline__ uint32_t f2tf(float f) {
    uint32_t u;
    asm("cvt.rna.tf32.f32 %0, %1;" : "=r"(u) : "f"(f));
    return u;
}
__device__ __forceinline__ void mma_tf32(float (&d)[4], const uint32_t (&a)[4],
                                         const uint32_t (&b)[2]) {
    asm volatile(
        "mma.sync.aligned.m16n8k8.row.col.f32.tf32.tf32.f32 "
        "{%0,%1,%2,%3}, {%4,%5,%6,%7}, {%8,%9}, {%0,%1,%2,%3};\n"
        : "+f"(d[0]), "+f"(d[1]), "+f"(d[2]), "+f"(d[3])
        : "r"(a[0]), "r"(a[1]), "r"(a[2]), "r"(a[3]), "r"(b[0]), "r"(b[1]));
}
__device__ __forceinline__ void cp16(uint32_t s, const void* g) {
    asm volatile("cp.async.cg.shared.global [%0], [%1], 16;\n" ::"r"(s), "l"(g));
}
__device__ __forceinline__ void cp_commit() { asm volatile("cp.async.commit_group;\n"); }
__device__ __forceinline__ void cp_wait1() { asm volatile("cp.async.wait_group 1;\n"); }
__device__ __forceinline__ void cp_wait0() { asm volatile("cp.async.wait_group 0;\n"); }

// ================= cache shift (runs on side stream, no consumer) =================
__global__ void shift_caches(const float4* __restrict__ ck,
                             const float4* __restrict__ cv,
                             float4* __restrict__ out) {
    long i = (long)blockIdx.x * 256 + threadIdx.x;
    const long PER = 8L * 4080 * 256;
    if (i < PER) {
        long b = i / (4080L * 256), r = i - b * (4080L * 256);
        out[CK_OFF / 4 + b * 1048576 + r] = ck[b * 1048576 + 4096 + r];
    } else if (i < 2 * PER) {
        long j = i - PER;
        long b = j / (4080L * 256), r = j - b * (4080L * 256);
        out[CV_OFF / 4 + b * 1048576 + r] = cv[b * 1048576 + 4096 + r];
    }
}

// ========== async double-buffered tf32 core: C += A(row,[M][K]) * B(row,[N][K])^T =====
template <int MF>
__device__ __forceinline__ void gemm_core_async(const float* __restrict__ A, long lda,
                                                const float* __restrict__ B, long ldb,
                                                int ktiles, float* As, float* Bs,
                                                float (&acc)[MF][4][4]) {
    const int tid = threadIdx.x;
    const int lane = tid & 31, wid = tid >> 5;
    const int wm = wid >> 2, wn = wid & 3;
    const int g = lane >> 2, tig = lane & 3;
    const int ASZW = MF * 32 * 20, BSZW = 128 * 20;
    uint32_t asS = (uint32_t)__cvta_generic_to_shared(As);
    uint32_t bsS = (uint32_t)__cvta_generic_to_shared(Bs);

    auto load_tile = [&](int t, int buf) {
        const float* Ak = A + t * 16;
        const float* Bk = B + t * 16;
#pragma unroll
        for (int i = 0; i < MF / 2; i++) {
            int v = tid + i * 256, r = v >> 2, c4 = v & 3;
            cp16(asS + (buf * ASZW + r * 20 + c4 * 4) * 4, Ak + (long)r * lda + c4 * 4);
        }
#pragma unroll
        for (int i = 0; i < 2; i++) {
            int v = tid + i * 256, r = v >> 2, c4 = v & 3;
            cp16(bsS + (buf * BSZW + r * 20 + c4 * 4) * 4, Bk + (long)r * ldb + c4 * 4);
        }
        cp_commit();
    };

    load_tile(0, 0);
    for (int t = 0; t < ktiles; t++) {
        if (t + 1 < ktiles) { load_tile(t + 1, (t + 1) & 1); cp_wait1(); }
        else cp_wait0();
        __syncthreads();
        const float* Af = As + (t & 1) * ASZW;
        const float* Bf = Bs + (t & 1) * BSZW;
#pragma unroll
        for (int ks = 0; ks < 16; ks += 8) {
            uint32_t a[MF][4], b[4][2];
#pragma unroll
            for (int mf = 0; mf < MF; mf++) {
                int m = wm * (MF * 16) + mf * 16;
                a[mf][0] = f2tf(Af[(m + g) * 20 + ks + tig]);
                a[mf][1] = f2tf(Af[(m + g + 8) * 20 + ks + tig]);
                a[mf][2] = f2tf(Af[(m + g) * 20 + ks + tig + 4]);
                a[mf][3] = f2tf(Af[(m + g + 8) * 20 + ks + tig + 4]);
            }
#pragma unroll
            for (int nf = 0; nf < 4; nf++) {
                int n = wn * 32 + nf * 8 + g;
                b[nf][0] = f2tf(Bf[n * 20 + ks + tig]);
                b[nf][1] = f2tf(Bf[n * 20 + ks + tig + 4]);
            }
#pragma unroll
            for (int mf = 0; mf < MF; mf++)
#pragma unroll
                for (int nf = 0; nf < 4; nf++) mma_tf32(acc[mf][nf], a[mf], b[nf]);
        }
        __syncthreads();
    }
}

template <int MF>
__device__ __forceinline__ void store_acc(float* __restrict__ C, long ldc,
                                          float (&acc)[MF][4][4]) {
    const int tid = threadIdx.x;
    const int lane = tid & 31, wid = tid >> 5;
    const int wm = wid >> 2, wn = wid & 3;
    const int g = lane >> 2, tig = lane & 3;
#pragma unroll
    for (int mf = 0; mf < MF; mf++) {
        int m = wm * (MF * 16) + mf * 16 + g;
#pragma unroll
        for (int nf = 0; nf < 4; nf++) {
            int n = wn * 32 + nf * 8 + 2 * tig;
            *(float2*)(C + (long)m * ldc + n) = make_float2(acc[mf][nf][0], acc[mf][nf][1]);
            *(float2*)(C + (long)(m + 8) * ldc + n) = make_float2(acc[mf][nf][2], acc[mf][nf][3]);
        }
    }
}

// ================= QKV projection (split-K=8) =================
__global__ void qkv_gemm_t(const float* __restrict__ X, const float* __restrict__ wq,
                           const float* __restrict__ wk, const float* __restrict__ wv) {
    __shared__ float As[2 * 128 * 20], Bs[2 * 128 * 20];
    int n0 = blockIdx.x * 128, split = blockIdx.y;
    const float* W;
    int nl;
    if (n0 < 4096) { W = wq; nl = n0; }
    else if (n0 < 5120) { W = wk; nl = n0 - 4096; }
    else { W = wv; nl = n0 - 5120; }
    float acc[4][4][4] = {};
    gemm_core_async<4>(X + split * 512, 4096, W + (long)nl * 4096 + split * 512, 4096, 32,
                       As, Bs, acc);
    store_acc<4>(g_qkv_part[split] + n0, QKV_N, acc);
}

// ================= RoPE + split reduce + scatter K/V (scratch + out tails) ===========
__global__ void rope_scatter(const float* __restrict__ freqs, float* __restrict__ out) {
    int m = blockIdx.x;
    int b = m >> 4, s = m & 15;
    long base = (long)m * QKV_N;
#pragma unroll 1
    for (int p = threadIdx.x; p < 2048; p += 256) {
        int h = p >> 6, i = p & 63;
        float re = 0.f, im = 0.f;
#pragma unroll
        for (int sp = 0; sp < QSPLIT; sp++) {
            re += g_qkv_part[sp][base + 2 * p];
            im += g_qkv_part[sp][base + 2 * p + 1];
        }
        float c = freqs[(s * 64 + i) * 2], sn = freqs[(s * 64 + i) * 2 + 1];
        long d = ((long)(b * 32 + h) * 16 + s) * 128 + 2 * i;
        g_xq[d] = (re * c - im * sn) * INV_SQRT_HD;
        g_xq[d + 1] = (re * sn + im * c) * INV_SQRT_HD;
    }
    float* cko = out + CK_OFF + (long)b * CACHE_PER_B + (long)(4080 + s) * 1024;
    float* knw = g_knew + (long)(b * 16 + s) * 1024;
#pragma unroll 1
    for (int p = threadIdx.x; p < 512; p += 256) {
        int i = p & 63;
        long o = base + 4096 + 2 * p;
        float re = 0.f, im = 0.f;
#pragma unroll
        for (int sp = 0; sp < QSPLIT; sp++) {
            re += g_qkv_part[sp][o];
            im += g_qkv_part[sp][o + 1];
        }
        float c = freqs[(s * 64 + i) * 2], sn = freqs[(s * 64 + i) * 2 + 1];
        float vr = re * c - im * sn, vi = re * sn + im * c;
        cko[2 * p] = vr; cko[2 * p + 1] = vi;
        knw[2 * p] = vr; knw[2 * p + 1] = vi;
    }
    float* cvo = out + CV_OFF + (long)b * CACHE_PER_B + (long)(4080 + s) * 1024;
    float* vnw = g_vnew + (long)(b * 16 + s) * 1024;
#pragma unroll 1
    for (int j = threadIdx.x; j < 1024; j += 256) {
        long o = base + 5120 + j;
        float v = 0.f;
#pragma unroll
        for (int sp = 0; sp < QSPLIT; sp++) v += g_qkv_part[sp][o];
        cvo[j] = v; vnw[j] = v;
    }
}

// ================= scores = q @ K^T + mask  (reads ORIGINAL cache at t+16) ==========
__global__ void scores_gemm_t(const float* __restrict__ ck, const float* __restrict__ mask) {
    __shared__ float As[2 * 64 * 20], Bs[2 * 128 * 20];
    int t0 = blockIdx.x * 128, pair = blockIdx.y;
    int b = pair >> 3, kv = pair & 7;
    const int tid = threadIdx.x;
    const int lane = tid & 31, wid = tid >> 5;
    const int wm = wid >> 2, wn = wid & 3;
    const int g = lane >> 2, tig = lane & 3;
    const int ASZW = 64 * 20, BSZW = 128 * 20;
    uint32_t asS = (uint32_t)__cvta_generic_to_shared(As);
    uint32_t bsS = (uint32_t)__cvta_generic_to_shared(Bs);

    const float* srcA;
    { int r = tid >> 2, c4 = tid & 3;
      srcA = g_xq + (long)pair * 8192 + r * 128 + c4 * 4; }
    const float* srcB[2];
#pragma unroll
    for (int i = 0; i < 2; i++) {
        int v = tid + i * 256, r = v >> 2, c4 = v & 3;
        int tg = t0 + r;
        srcB[i] = (tg < 4080 ? ck + (long)b * CACHE_PER_B + (long)(tg + 16) * 1024
                             : g_knew + (long)(b * 16 + tg - 4080) * 1024) + kv * 128 + c4 * 4;
    }
    auto load_tile = [&](int t, int buf) {
        { int r = tid >> 2, c4 = tid & 3;
          cp16(asS + (buf * ASZW + r * 20 + c4 * 4) * 4, srcA + t * 16); }
#pragma unroll
        for (int i = 0; i < 2; i++) {
            int v = tid + i * 256, r = v >> 2, c4 = v & 3;
            cp16(bsS + (buf * BSZW + r * 20 + c4 * 4) * 4, srcB[i] + t * 16);
        }
        cp_commit();
    };

    float acc[2][4][4] = {};
    load_tile(0, 0);
    for (int t = 0; t < 8; t++) {
        if (t + 1 < 8) { load_tile(t + 1, (t + 1) & 1); cp_wait1(); }
        else cp_wait0();
        __syncthreads();
        const float* Af = As + (t & 1) * ASZW;
        const float* Bf = Bs + (t & 1) * BSZW;
#pragma unroll
        for (int ks = 0; ks < 16; ks += 8) {
            uint32_t a[2][4], bb[4][2];
#pragma unroll
            for (int mf = 0; mf < 2; mf++) {
                int m = wm * 32 + mf * 16;
                a[mf][0] = f2tf(Af[(m + g) * 20 + ks + tig]);
                a[mf][1] = f2tf(Af[(m + g + 8) * 20 + ks + tig]);
                a[mf][2] = f2tf(Af[(m + g) * 20 + ks + tig + 4]);
                a[mf][3] = f2tf(Af[(m + g + 8) * 20 + ks + tig + 4]);
            }
#pragma unroll
            for (int nf = 0; nf < 4; nf++) {
                int n = wn * 32 + nf * 8 + g;
                bb[nf][0] = f2tf(Bf[n * 20 + ks + tig]);
                bb[nf][1] = f2tf(Bf[n * 20 + ks + tig + 4]);
            }
#pragma unroll
            for (int mf = 0; mf < 2; mf++)
#pragma unroll
                for (int nf = 0; nf < 4; nf++) mma_tf32(acc[mf][nf], a[mf], bb[nf]);
        }
        __syncthreads();
    }
#pragma unroll
    for (int mf = 0; mf < 2; mf++) {
        int m = wm * 32 + mf * 16 + g;
#pragma unroll
        for (int nf = 0; nf < 4; nf++) {
            int n = t0 + wn * 32 + nf * 8 + 2 * tig;
            {
                long row = (long)pair * 64 + m; int q = m & 15;
                g_scores[row * 4096 + n]     = acc[mf][nf][0] + mask[q * 4096 + n];
                g_scores[row * 4096 + n + 1] = acc[mf][nf][1] + mask[q * 4096 + n + 1];
            }
            {
                long row = (long)pair * 64 + m + 8; int q = (m + 8) & 15;
                g_scores[row * 4096 + n]     = acc[mf][nf][2] + mask[q * 4096 + n];
                g_scores[row * 4096 + n + 1] = acc[mf][nf][3] + mask[q * 4096 + n + 1];
            }
        }
    }
}

// ================= row softmax over 4096 (float4 vectorized) =================
__global__ void softmax_k() {
    float4* row = (float4*)(g_scores + (long)blockIdx.x * 4096);  // 1024 float4
    int tid = threadIdx.x;
    float4 v[4];
    float mx = -1e30f;
#pragma unroll
    for (int j = 0; j < 4; j++) {
        v[j] = row[tid + j * 256];
        mx = fmaxf(mx, fmaxf(fmaxf(v[j].x, v[j].y), fmaxf(v[j].z, v[j].w)));
    }
    __shared__ float red[8];
#pragma unroll
    for (int o = 16; o; o >>= 1) mx = fmaxf(mx, __shfl_xor_sync(0xffffffffu, mx, o));
    if ((tid & 31) == 0) red[tid >> 5] = mx;
    __syncthreads();
    mx = red[0];
#pragma unroll
    for (int i = 1; i < 8; i++) mx = fmaxf(mx, red[i]);
    float s = 0.f;
#pragma unroll
    for (int j = 0; j < 4; j++) {
        v[j].x = __expf(v[j].x - mx); v[j].y = __expf(v[j].y - mx);
        v[j].z = __expf(v[j].z - mx); v[j].w = __expf(v[j].w - mx);
        s += v[j].x + v[j].y + v[j].z + v[j].w;
    }
#pragma unroll
    for (int o = 16; o; o >>= 1) s += __shfl_xor_sync(0xffffffffu, s, o);
    __syncthreads();
    if ((tid & 31) == 0) red[tid >> 5] = s;
    __syncthreads();
    float tot = 0.f;
#pragma unroll
    for (int i = 0; i < 8; i++) tot += red[i];
    float inv = 1.0f / tot;
#pragma unroll
    for (int j = 0; j < 4; j++) {
        v[j].x *= inv; v[j].y *= inv; v[j].z *= inv; v[j].w *= inv;
        row[tid + j * 256] = v[j];
    }
}

// ================= attn = probs @ V  (split-K=4, BK=32; V from original cache) =======
#define AV_A_W (64 * 36)
#define AV_V_W (32 * 136)
#define AV_SMEM (2 * (AV_A_W + AV_V_W) * 4)   // 53,248 B -> dynamic smem
__global__ void attnv_gemm_t(const float* __restrict__ cv) {
    extern __shared__ float av_sh[];
    float* As = av_sh;                       // 2 x 64x36
    float* Vs = av_sh + 2 * AV_A_W;          // 2 x 32x136
    int pair = blockIdx.x, split = blockIdx.y;
    int b = pair >> 3, kvv = pair & 7;
    const int tid = threadIdx.x;
    const int lane = tid & 31, wid = tid >> 5;
    const int wm = wid >> 2, wn = wid & 3;
    const int g = lane >> 2, tig = lane & 3;
    uint32_t asS = (uint32_t)__cvta_generic_to_shared(As);
    uint32_t vsS = (uint32_t)__cvta_generic_to_shared(Vs);
    const float* A = g_scores + (long)pair * 64 * 4096 + split * 1024;
    int k0 = split * 1024;

    auto load_tile = [&](int t, int buf) {
#pragma unroll
        for (int i = 0; i < 2; i++) {
            int v = tid + i * 256, r = v >> 3, c4 = v & 7;
            cp16(asS + (buf * AV_A_W + r * 36 + c4 * 4) * 4,
                 A + (long)r * 4096 + t * 32 + c4 * 4);
        }
#pragma unroll
        for (int i = 0; i < 4; i++) {
            int v = tid + i * 256;
            int kk = v >> 5, n4 = v & 31;
            int tg = k0 + t * 32 + kk;
            const float* src =
                (tg < 4080 ? cv + (long)b * CACHE_PER_B + (long)(tg + 16) * 1024
                           : g_vnew + (long)(b * 16 + tg - 4080) * 1024) + kvv * 128 + n4 * 4;
            cp16(vsS + (buf * AV_V_W + kk * 136 + n4 * 4) * 4, src);
        }
        cp_commit();
    };

    float acc[2][4][4] = {};
    load_tile(0, 0);
    for (int t = 0; t < 32; t++) {
        if (t + 1 < 32) { load_tile(t + 1, (t + 1) & 1); cp_wait1(); }
        else cp_wait0();
        __syncthreads();
        const float* Af = As + (t & 1) * AV_A_W;
        const float* Vf = Vs + (t & 1) * AV_V_W;
#pragma unroll
        for (int ks = 0; ks < 32; ks += 8) {
            uint32_t a[2][4], bb[4][2];
#pragma unroll
            for (int mf = 0; mf < 2; mf++) {
                int m = wm * 32 + mf * 16;
                a[mf][0] = f2tf(Af[(m + g) * 36 + ks + tig]);
                a[mf][1] = f2tf(Af[(m + g + 8) * 36 + ks + tig]);
                a[mf][2] = f2tf(Af[(m + g) * 36 + ks + tig + 4]);
                a[mf][3] = f2tf(Af[(m + g + 8) * 36 + ks + tig + 4]);
            }
#pragma unroll
            for (int nf = 0; nf < 4; nf++) {
                int n = wn * 32 + nf * 8 + g;
                bb[nf][0] = f2tf(Vf[(ks + tig) * 136 + n]);
                bb[nf][1] = f2tf(Vf[(ks + tig + 4) * 136 + n]);
            }
#pragma unroll
            for (int mf = 0; mf < 2; mf++)
#pragma unroll
                for (int nf = 0; nf < 4; nf++) mma_tf32(acc[mf][nf], a[mf], bb[nf]);
        }
        __syncthreads();
    }
    store_acc<2>(g_attn_part[split] + (long)pair * 64 * 128, 128, acc);
}

__global__ void attnv_reduce() {
    long idx = (long)blockIdx.x * 256 + threadIdx.x;  // float4 index
    long o = idx * 4;
    float4 p0 = ((const float4*)g_attn_part[0])[idx];
    float4 p1 = ((const float4*)g_attn_part[1])[idx];
    float4 p2 = ((const float4*)g_attn_part[2])[idx];
    float4 p3 = ((const float4*)g_attn_part[3])[idx];
    float4 s = make_float4(p0.x + p1.x + p2.x + p3.x, p0.y + p1.y + p2.y + p3.y,
                           p0.z + p1.z + p2.z + p3.z, p0.w + p1.w + p2.w + p3.w);
    int pair = (int)(o >> 13), r = (int)((o >> 7) & 63), d = (int)(o & 127);
    int b = pair >> 3, kv = pair & 7, hp = r >> 4, q = r & 15;
    *(float4*)(g_attn + ((long)(b * 16 + q) * 4096 + (kv * 4 + hp) * 128 + d)) = s;
}

// ================= out = attn @ wo^T (split-K=8) =================
__global__ void out_gemm_t(const float* __restrict__ wo) {
    __shared__ float As[2 * 128 * 20], Bs[2 * 128 * 20];
    int n0 = blockIdx.x * 128, split = blockIdx.y;
    float acc[4][4][4] = {};
    gemm_core_async<4>(g_attn + split * 512, 4096, wo + (long)n0 * 4096 + split * 512, 4096,
                       32, As, Bs, acc);
    store_acc<4>(g_out_part[split] + n0, 4096, acc);
}

__global__ void out_reduce(float* __restrict__ out) {
    long idx = (long)blockIdx.x * 256 + threadIdx.x;
    float4 s = make_float4(0.f, 0.f, 0.f, 0.f);
#pragma unroll
    for (int sp = 0; sp < OSPLIT; sp++) {
        float4 p = ((const float4*)g_out_part[sp])[idx];
        s.x += p.x; s.y += p.y; s.z += p.z; s.w += p.w;
    }
    ((float4*)out)[idx] = s;
}

// ================= launch =================
extern "C" void kernel_launch(void* const* d_in, const int* in_sizes, int n_in,
                              void* d_out, int out_size) {
    const float* x     = (const float*)d_in[0];
    const float* mask  = (const float*)d_in[1];
    const float* freqs = (const float*)d_in[2];
    const float* ck    = (const float*)d_in[3];
    const float* cv    = (const float*)d_in[4];
    const float* wq    = (const float*)d_in[5];
    const float* wk    = (const float*)d_in[6];
    const float* wv    = (const float*)d_in[7];
    const float* wo    = (const float*)d_in[8];
    float* out = (float*)d_out;

    // one-time side-stream setup (host objects only; no device memory)
    static cudaStream_t s_copy = nullptr;
    static cudaEvent_t ev_fork = nullptr, ev_join = nullptr;
    if (!s_copy) {
        cudaStreamCreateWithFlags(&s_copy, cudaStreamNonBlocking);
        cudaEventCreateWithFlags(&ev_fork, cudaEventDisableTiming);
        cudaEventCreateWithFlags(&ev_join, cudaEventDisableTiming);
        cudaFuncSetAttribute(attnv_gemm_t, cudaFuncAttributeMaxDynamicSharedMemorySize,
                             AV_SMEM);
    }

    // fork: cache shift overlaps all compute (nothing downstream reads shifted copy)
    cudaEventRecord(ev_fork, 0);
    cudaStreamWaitEvent(s_copy, ev_fork, 0);
    shift_caches<<<65280, 256, 0, s_copy>>>((const float4*)ck, (const float4*)cv,
                                            (float4*)out);
    cudaEventRecord(ev_join, s_copy);

    // compute chain on main stream, reading ORIGINAL caches
    qkv_gemm_t<<<dim3(48, QSPLIT), 256>>>(x, wq, wk, wv);
    rope_scatter<<<128, 256>>>(freqs, out);
    scores_gemm_t<<<dim3(32, 64), 256>>>(ck, mask);
    softmax_k<<<4096, 256>>>();
    attnv_gemm_t<<<dim3(64, 4), 256, AV_SMEM>>>(cv);
    attnv_reduce<<<512, 256>>>();
    out_gemm_t<<<dim3(32, OSPLIT), 256>>>(wo);
    out_reduce<<<512, 256>>>(out);

    // join: shift must complete before harness observes d_out
    cudaStreamWaitEvent(0, ev_join, 0);
}

// round 16
// speedup vs baseline: 1.6434x; 1.0128x over previous
#include <cuda_runtime.h>
#include <cstdint>

// ---- problem constants ----
#define BSZ 8
#define SEQLEN 16
#define DIM 4096
#define NH 32
#define NKV 8
#define HD 128
#define CACHE 4096
#define M_TOT 128
#define QKV_N 6144
#define CACHE_PER_B 4194304L // 4096*8*128
#define CK_OFF 524288L
#define CV_OFF 34078720L
#define INV_SQRT_HD 0.08838834764831845f
#define QSPLIT 8
#define OSPLIT 8

// ---- scratch ----
__device__ float g_qkv_part[QSPLIT][M_TOT * QKV_N];
__device__ float g_xq[64 * 64 * 128];            // [pair*64+row][d], pre-scaled 1/sqrt(hd)
__device__ float g_knew[BSZ * 16 * 1024];        // [b*16+s][kv*128+d] rope'd new K
__device__ float g_vnew[BSZ * 16 * 1024];        // new V
__device__ float g_scores[4096 * 4096];          // [pair*64+r][t]  (64MB, L2-resident)
__device__ float g_attn_part[4][64 * 64 * 128];
__device__ float g_attn[M_TOT * 4096];
__device__ float g_out_part[OSPLIT][M_TOT * DIM];

// ---- helpers ----
__device__ __forceinline__ uint32_t f2tf(float f) {
    uint32_t u;
    asm("cvt.rna.tf32.f32 %0, %1;" : "=r"(u) : "f"(f));
    return u;
}
__device__ __forceinline__ void mma_tf32(float (&d)[4], const uint32_t (&a)[4],
                                         const uint32_t (&b)[2]) {
    asm volatile(
        "mma.sync.aligned.m16n8k8.row.col.f32.tf32.tf32.f32 "
        "{%0,%1,%2,%3}, {%4,%5,%6,%7}, {%8,%9}, {%0,%1,%2,%3};\n"
        : "+f"(d[0]), "+f"(d[1]), "+f"(d[2]), "+f"(d[3])
        : "r"(a[0]), "r"(a[1]), "r"(a[2]), "r"(a[3]), "r"(b[0]), "r"(b[1]));
}
__device__ __forceinline__ void cp16(uint32_t s, const void* g) {
    asm volatile("cp.async.cg.shared.global [%0], [%1], 16;\n" ::"r"(s), "l"(g));
}
__device__ __forceinline__ void cp_commit() { asm volatile("cp.async.commit_group;\n"); }
__device__ __forceinline__ void cp_wait1() { asm volatile("cp.async.wait_group 1;\n"); }
__device__ __forceinline__ void cp_wait0() { asm volatile("cp.async.wait_group 0;\n"); }

// ================= cache shift (runs on side stream, no consumer) =================
__global__ void shift_caches(const float4* __restrict__ ck,
                             const float4* __restrict__ cv,
                             float4* __restrict__ out) {
    long i = (long)blockIdx.x * 256 + threadIdx.x;
    const long PER = 8L * 4080 * 256;
    if (i < PER) {
        long b = i / (4080L * 256), r = i - b * (4080L * 256);
        out[CK_OFF / 4 + b * 1048576 + r] = ck[b * 1048576 + 4096 + r];
    } else if (i < 2 * PER) {
        long j = i - PER;
        long b = j / (4080L * 256), r = j - b * (4080L * 256);
        out[CV_OFF / 4 + b * 1048576 + r] = cv[b * 1048576 + 4096 + r];
    }
}

// ========== async double-buffered tf32 core (BK=16): C += A * B^T ==========
template <int MF>
__device__ __forceinline__ void gemm_core_async(const float* __restrict__ A, long lda,
                                                const float* __restrict__ B, long ldb,
                                                int ktiles, float* As, float* Bs,
                                                float (&acc)[MF][4][4]) {
    const int tid = threadIdx.x;
    const int lane = tid & 31, wid = tid >> 5;
    const int wm = wid >> 2, wn = wid & 3;
    const int g = lane >> 2, tig = lane & 3;
    const int ASZW = MF * 32 * 20, BSZW = 128 * 20;
    uint32_t asS = (uint32_t)__cvta_generic_to_shared(As);
    uint32_t bsS = (uint32_t)__cvta_generic_to_shared(Bs);

    auto load_tile = [&](int t, int buf) {
        const float* Ak = A + t * 16;
        const float* Bk = B + t * 16;
#pragma unroll
        for (int i = 0; i < MF / 2; i++) {
            int v = tid + i * 256, r = v >> 2, c4 = v & 3;
            cp16(asS + (buf * ASZW + r * 20 + c4 * 4) * 4, Ak + (long)r * lda + c4 * 4);
        }
#pragma unroll
        for (int i = 0; i < 2; i++) {
            int v = tid + i * 256, r = v >> 2, c4 = v & 3;
            cp16(bsS + (buf * BSZW + r * 20 + c4 * 4) * 4, Bk + (long)r * ldb + c4 * 4);
        }
        cp_commit();
    };

    load_tile(0, 0);
    for (int t = 0; t < ktiles; t++) {
        if (t + 1 < ktiles) { load_tile(t + 1, (t + 1) & 1); cp_wait1(); }
        else cp_wait0();
        __syncthreads();
        const float* Af = As + (t & 1) * ASZW;
        const float* Bf = Bs + (t & 1) * BSZW;
#pragma unroll
        for (int ks = 0; ks < 16; ks += 8) {
            uint32_t a[MF][4], b[4][2];
#pragma unroll
            for (int mf = 0; mf < MF; mf++) {
                int m = wm * (MF * 16) + mf * 16;
                a[mf][0] = f2tf(Af[(m + g) * 20 + ks + tig]);
                a[mf][1] = f2tf(Af[(m + g + 8) * 20 + ks + tig]);
                a[mf][2] = f2tf(Af[(m + g) * 20 + ks + tig + 4]);
                a[mf][3] = f2tf(Af[(m + g + 8) * 20 + ks + tig + 4]);
            }
#pragma unroll
            for (int nf = 0; nf < 4; nf++) {
                int n = wn * 32 + nf * 8 + g;
                b[nf][0] = f2tf(Bf[n * 20 + ks + tig]);
                b[nf][1] = f2tf(Bf[n * 20 + ks + tig + 4]);
            }
#pragma unroll
            for (int mf = 0; mf < MF; mf++)
#pragma unroll
                for (int nf = 0; nf < 4; nf++) mma_tf32(acc[mf][nf], a[mf], b[nf]);
        }
        __syncthreads();
    }
}

template <int MF>
__device__ __forceinline__ void store_acc(float* __restrict__ C, long ldc,
                                          float (&acc)[MF][4][4]) {
    const int tid = threadIdx.x;
    const int lane = tid & 31, wid = tid >> 5;
    const int wm = wid >> 2, wn = wid & 3;
    const int g = lane >> 2, tig = lane & 3;
#pragma unroll
    for (int mf = 0; mf < MF; mf++) {
        int m = wm * (MF * 16) + mf * 16 + g;
#pragma unroll
        for (int nf = 0; nf < 4; nf++) {
            int n = wn * 32 + nf * 8 + 2 * tig;
            *(float2*)(C + (long)m * ldc + n) = make_float2(acc[mf][nf][0], acc[mf][nf][1]);
            *(float2*)(C + (long)(m + 8) * ldc + n) = make_float2(acc[mf][nf][2], acc[mf][nf][3]);
        }
    }
}

// ================= QKV projection (split-K=8) =================
__global__ void qkv_gemm_t(const float* __restrict__ X, const float* __restrict__ wq,
                           const float* __restrict__ wk, const float* __restrict__ wv) {
    __shared__ float As[2 * 128 * 20], Bs[2 * 128 * 20];
    int n0 = blockIdx.x * 128, split = blockIdx.y;
    const float* W;
    int nl;
    if (n0 < 4096) { W = wq; nl = n0; }
    else if (n0 < 5120) { W = wk; nl = n0 - 4096; }
    else { W = wv; nl = n0 - 5120; }
    float acc[4][4][4] = {};
    gemm_core_async<4>(X + split * 512, 4096, W + (long)nl * 4096 + split * 512, 4096, 32,
                       As, Bs, acc);
    store_acc<4>(g_qkv_part[split] + n0, QKV_N, acc);
}

// ================= RoPE + split reduce + scatter K/V (scratch + out tails) ===========
__global__ void rope_scatter(const float* __restrict__ freqs, float* __restrict__ out) {
    int m = blockIdx.x;
    int b = m >> 4, s = m & 15;
    long base = (long)m * QKV_N;
#pragma unroll 1
    for (int p = threadIdx.x; p < 2048; p += 256) {
        int h = p >> 6, i = p & 63;
        float re = 0.f, im = 0.f;
#pragma unroll
        for (int sp = 0; sp < QSPLIT; sp++) {
            re += g_qkv_part[sp][base + 2 * p];
            im += g_qkv_part[sp][base + 2 * p + 1];
        }
        float c = freqs[(s * 64 + i) * 2], sn = freqs[(s * 64 + i) * 2 + 1];
        long d = ((long)(b * 32 + h) * 16 + s) * 128 + 2 * i;
        g_xq[d] = (re * c - im * sn) * INV_SQRT_HD;
        g_xq[d + 1] = (re * sn + im * c) * INV_SQRT_HD;
    }
    float* cko = out + CK_OFF + (long)b * CACHE_PER_B + (long)(4080 + s) * 1024;
    float* knw = g_knew + (long)(b * 16 + s) * 1024;
#pragma unroll 1
    for (int p = threadIdx.x; p < 512; p += 256) {
        int i = p & 63;
        long o = base + 4096 + 2 * p;
        float re = 0.f, im = 0.f;
#pragma unroll
        for (int sp = 0; sp < QSPLIT; sp++) {
            re += g_qkv_part[sp][o];
            im += g_qkv_part[sp][o + 1];
        }
        float c = freqs[(s * 64 + i) * 2], sn = freqs[(s * 64 + i) * 2 + 1];
        float vr = re * c - im * sn, vi = re * sn + im * c;
        cko[2 * p] = vr; cko[2 * p + 1] = vi;
        knw[2 * p] = vr; knw[2 * p + 1] = vi;
    }
    float* cvo = out + CV_OFF + (long)b * CACHE_PER_B + (long)(4080 + s) * 1024;
    float* vnw = g_vnew + (long)(b * 16 + s) * 1024;
#pragma unroll 1
    for (int j = threadIdx.x; j < 1024; j += 256) {
        long o = base + 5120 + j;
        float v = 0.f;
#pragma unroll
        for (int sp = 0; sp < QSPLIT; sp++) v += g_qkv_part[sp][o];
        cvo[j] = v; vnw[j] = v;
    }
}

// ================= scores = q @ K^T + mask  (BK=32, reads ORIGINAL cache) ==========
#define SC_A_W (64 * 36)
#define SC_B_W (128 * 36)
#define SC_SMEM (2 * (SC_A_W + SC_B_W) * 4)   // 55,296 B -> dynamic smem
__global__ void scores_gemm_t(const float* __restrict__ ck, const float* __restrict__ mask) {
    extern __shared__ float sc_sh[];
    float* As = sc_sh;                 // 2 x 64x36
    float* Bs = sc_sh + 2 * SC_A_W;    // 2 x 128x36
    int t0 = blockIdx.x * 128, pair = blockIdx.y;
    int b = pair >> 3, kv = pair & 7;
    const int tid = threadIdx.x;
    const int lane = tid & 31, wid = tid >> 5;
    const int wm = wid >> 2, wn = wid & 3;
    const int g = lane >> 2, tig = lane & 3;
    uint32_t asS = (uint32_t)__cvta_generic_to_shared(As);
    uint32_t bsS = (uint32_t)__cvta_generic_to_shared(Bs);

    // fixed row sources
    const float* srcA[2];
#pragma unroll
    for (int i = 0; i < 2; i++) {
        int v = tid + i * 256, r = v >> 3, c4 = v & 7;
        srcA[i] = g_xq + (long)pair * 8192 + r * 128 + c4 * 4;
    }
    const float* srcB[4];
#pragma unroll
    for (int i = 0; i < 4; i++) {
        int v = tid + i * 256, r = v >> 3, c4 = v & 7;
        int tg = t0 + r;
        srcB[i] = (tg < 4080 ? ck + (long)b * CACHE_PER_B + (long)(tg + 16) * 1024
                             : g_knew + (long)(b * 16 + tg - 4080) * 1024) + kv * 128 + c4 * 4;
    }
    auto load_tile = [&](int t, int buf) {
#pragma unroll
        for (int i = 0; i < 2; i++) {
            int v = tid + i * 256, r = v >> 3, c4 = v & 7;
            cp16(asS + (buf * SC_A_W + r * 36 + c4 * 4) * 4, srcA[i] + t * 32);
        }
#pragma unroll
        for (int i = 0; i < 4; i++) {
            int v = tid + i * 256, r = v >> 3, c4 = v & 7;
            cp16(bsS + (buf * SC_B_W + r * 36 + c4 * 4) * 4, srcB[i] + t * 32);
        }
        cp_commit();
    };

    float acc[2][4][4] = {};
    load_tile(0, 0);
    for (int t = 0; t < 4; t++) {
        if (t + 1 < 4) { load_tile(t + 1, (t + 1) & 1); cp_wait1(); }
        else cp_wait0();
        __syncthreads();
        const float* Af = As + (t & 1) * SC_A_W;
        const float* Bf = Bs + (t & 1) * SC_B_W;
#pragma unroll
        for (int ks = 0; ks < 32; ks += 8) {
            uint32_t a[2][4], bb[4][2];
#pragma unroll
            for (int mf = 0; mf < 2; mf++) {
                int m = wm * 32 + mf * 16;
                a[mf][0] = f2tf(Af[(m + g) * 36 + ks + tig]);
                a[mf][1] = f2tf(Af[(m + g + 8) * 36 + ks + tig]);
                a[mf][2] = f2tf(Af[(m + g) * 36 + ks + tig + 4]);
                a[mf][3] = f2tf(Af[(m + g + 8) * 36 + ks + tig + 4]);
            }
#pragma unroll
            for (int nf = 0; nf < 4; nf++) {
                int n = wn * 32 + nf * 8 + g;
                bb[nf][0] = f2tf(Bf[n * 36 + ks + tig]);
                bb[nf][1] = f2tf(Bf[n * 36 + ks + tig + 4]);
            }
#pragma unroll
            for (int mf = 0; mf < 2; mf++)
#pragma unroll
                for (int nf = 0; nf < 4; nf++) mma_tf32(acc[mf][nf], a[mf], bb[nf]);
        }
        __syncthreads();
    }
#pragma unroll
    for (int mf = 0; mf < 2; mf++) {
        int m = wm * 32 + mf * 16 + g;
#pragma unroll
        for (int nf = 0; nf < 4; nf++) {
            int n = t0 + wn * 32 + nf * 8 + 2 * tig;
            {
                long row = (long)pair * 64 + m; int q = m & 15;
                g_scores[row * 4096 + n]     = acc[mf][nf][0] + mask[q * 4096 + n];
                g_scores[row * 4096 + n + 1] = acc[mf][nf][1] + mask[q * 4096 + n + 1];
            }
            {
                long row = (long)pair * 64 + m + 8; int q = (m + 8) & 15;
                g_scores[row * 4096 + n]     = acc[mf][nf][2] + mask[q * 4096 + n];
                g_scores[row * 4096 + n + 1] = acc[mf][nf][3] + mask[q * 4096 + n + 1];
            }
        }
    }
}

// ================= row softmax over 4096 (float4 vectorized) =================
__global__ void softmax_k() {
    float4* row = (float4*)(g_scores + (long)blockIdx.x * 4096);  // 1024 float4
    int tid = threadIdx.x;
    float4 v[4];
    float mx = -1e30f;
#pragma unroll
    for (int j = 0; j < 4; j++) {
        v[j] = row[tid + j * 256];
        mx = fmaxf(mx, fmaxf(fmaxf(v[j].x, v[j].y), fmaxf(v[j].z, v[j].w)));
    }
    __shared__ float red[8];
#pragma unroll
    for (int o = 16; o; o >>= 1) mx = fmaxf(mx, __shfl_xor_sync(0xffffffffu, mx, o));
    if ((tid & 31) == 0) red[tid >> 5] = mx;
    __syncthreads();
    mx = red[0];
#pragma unroll
    for (int i = 1; i < 8; i++) mx = fmaxf(mx, red[i]);
    float s = 0.f;
#pragma unroll
    for (int j = 0; j < 4; j++) {
        v[j].x = __expf(v[j].x - mx); v[j].y = __expf(v[j].y - mx);
        v[j].z = __expf(v[j].z - mx); v[j].w = __expf(v[j].w - mx);
        s += v[j].x + v[j].y + v[j].z + v[j].w;
    }
#pragma unroll
    for (int o = 16; o; o >>= 1) s += __shfl_xor_sync(0xffffffffu, s, o);
    __syncthreads();
    if ((tid & 31) == 0) red[tid >> 5] = s;
    __syncthreads();
    float tot = 0.f;
#pragma unroll
    for (int i = 0; i < 8; i++) tot += red[i];
    float inv = 1.0f / tot;
#pragma unroll
    for (int j = 0; j < 4; j++) {
        v[j].x *= inv; v[j].y *= inv; v[j].z *= inv; v[j].w *= inv;
        row[tid + j * 256] = v[j];
    }
}

// ================= attn = probs @ V  (split-K=4, BK=32; V from original cache) =======
#define AV_A_W (64 * 36)
#define AV_V_W (32 * 136)
#define AV_SMEM (2 * (AV_A_W + AV_V_W) * 4)   // 53,248 B -> dynamic smem
__global__ void attnv_gemm_t(const float* __restrict__ cv) {
    extern __shared__ float av_sh[];
    float* As = av_sh;                       // 2 x 64x36
    float* Vs = av_sh + 2 * AV_A_W;          // 2 x 32x136
    int pair = blockIdx.x, split = blockIdx.y;
    int b = pair >> 3, kvv = pair & 7;
    const int tid = threadIdx.x;
    const int lane = tid & 31, wid = tid >> 5;
    const int wm = wid >> 2, wn = wid & 3;
    const int g = lane >> 2, tig = lane & 3;
    uint32_t asS = (uint32_t)__cvta_generic_to_shared(As);
    uint32_t vsS = (uint32_t)__cvta_generic_to_shared(Vs);
    const float* A = g_scores + (long)pair * 64 * 4096 + split * 1024;
    int k0 = split * 1024;

    auto load_tile = [&](int t, int buf) {
#pragma unroll
        for (int i = 0; i < 2; i++) {
            int v = tid + i * 256, r = v >> 3, c4 = v & 7;
            cp16(asS + (buf * AV_A_W + r * 36 + c4 * 4) * 4,
                 A + (long)r * 4096 + t * 32 + c4 * 4);
        }
#pragma unroll
        for (int i = 0; i < 4; i++) {
            int v = tid + i * 256;
            int kk = v >> 5, n4 = v & 31;
            int tg = k0 + t * 32 + kk;
            const float* src =
                (tg < 4080 ? cv + (long)b * CACHE_PER_B + (long)(tg + 16) * 1024
                           : g_vnew + (long)(b * 16 + tg - 4080) * 1024) + kvv * 128 + n4 * 4;
            cp16(vsS + (buf * AV_V_W + kk * 136 + n4 * 4) * 4, src);
        }
        cp_commit();
    };

    float acc[2][4][4] = {};
    load_tile(0, 0);
    for (int t = 0; t < 32; t++) {
        if (t + 1 < 32) { load_tile(t + 1, (t + 1) & 1); cp_wait1(); }
        else cp_wait0();
        __syncthreads();
        const float* Af = As + (t & 1) * AV_A_W;
        const float* Vf = Vs + (t & 1) * AV_V_W;
#pragma unroll
        for (int ks = 0; ks < 32; ks += 8) {
            uint32_t a[2][4], bb[4][2];
#pragma unroll
            for (int mf = 0; mf < 2; mf++) {
                int m = wm * 32 + mf * 16;
                a[mf][0] = f2tf(Af[(m + g) * 36 + ks + tig]);
                a[mf][1] = f2tf(Af[(m + g + 8) * 36 + ks + tig]);
                a[mf][2] = f2tf(Af[(m + g) * 36 + ks + tig + 4]);
                a[mf][3] = f2tf(Af[(m + g + 8) * 36 + ks + tig + 4]);
            }
#pragma unroll
            for (int nf = 0; nf < 4; nf++) {
                int n = wn * 32 + nf * 8 + g;
                bb[nf][0] = f2tf(Vf[(ks + tig) * 136 + n]);
                bb[nf][1] = f2tf(Vf[(ks + tig + 4) * 136 + n]);
            }
#pragma unroll
            for (int mf = 0; mf < 2; mf++)
#pragma unroll
                for (int nf = 0; nf < 4; nf++) mma_tf32(acc[mf][nf], a[mf], bb[nf]);
        }
        __syncthreads();
    }
    store_acc<2>(g_attn_part[split] + (long)pair * 64 * 128, 128, acc);
}

__global__ void attnv_reduce() {
    long idx = (long)blockIdx.x * 256 + threadIdx.x;  // float4 index
    long o = idx * 4;
    float4 p0 = ((const float4*)g_attn_part[0])[idx];
    float4 p1 = ((const float4*)g_attn_part[1])[idx];
    float4 p2 = ((const float4*)g_attn_part[2])[idx];
    float4 p3 = ((const float4*)g_attn_part[3])[idx];
    float4 s = make_float4(p0.x + p1.x + p2.x + p3.x, p0.y + p1.y + p2.y + p3.y,
                           p0.z + p1.z + p2.z + p3.z, p0.w + p1.w + p2.w + p3.w);
    int pair = (int)(o >> 13), r = (int)((o >> 7) & 63), d = (int)(o & 127);
    int b = pair >> 3, kv = pair & 7, hp = r >> 4, q = r & 15;
    *(float4*)(g_attn + ((long)(b * 16 + q) * 4096 + (kv * 4 + hp) * 128 + d)) = s;
}

// ================= out = attn @ wo^T (split-K=8) =================
__global__ void out_gemm_t(const float* __restrict__ wo) {
    __shared__ float As[2 * 128 * 20], Bs[2 * 128 * 20];
    int n0 = blockIdx.x * 128, split = blockIdx.y;
    float acc[4][4][4] = {};
    gemm_core_async<4>(g_attn + split * 512, 4096, wo + (long)n0 * 4096 + split * 512, 4096,
                       32, As, Bs, acc);
    store_acc<4>(g_out_part[split] + n0, 4096, acc);
}

__global__ void out_reduce(float* __restrict__ out) {
    long idx = (long)blockIdx.x * 256 + threadIdx.x;
    float4 s = make_float4(0.f, 0.f, 0.f, 0.f);
#pragma unroll
    for (int sp = 0; sp < OSPLIT; sp++) {
        float4 p = ((const float4*)g_out_part[sp])[idx];
        s.x += p.x; s.y += p.y; s.z += p.z; s.w += p.w;
    }
    ((float4*)out)[idx] = s;
}

// ================= launch =================
extern "C" void kernel_launch(void* const* d_in, const int* in_sizes, int n_in,
                              void* d_out, int out_size) {
    const float* x     = (const float*)d_in[0];
    const float* mask  = (const float*)d_in[1];
    const float* freqs = (const float*)d_in[2];
    const float* ck    = (const float*)d_in[3];
    const float* cv    = (const float*)d_in[4];
    const float* wq    = (const float*)d_in[5];
    const float* wk    = (const float*)d_in[6];
    const float* wv    = (const float*)d_in[7];
    const float* wo    = (const float*)d_in[8];
    float* out = (float*)d_out;

    // one-time side-stream setup (host objects only; no device memory)
    static cudaStream_t s_copy = nullptr;
    static cudaEvent_t ev_fork = nullptr, ev_join = nullptr;
    if (!s_copy) {
        cudaStreamCreateWithFlags(&s_copy, cudaStreamNonBlocking);
        cudaEventCreateWithFlags(&ev_fork, cudaEventDisableTiming);
        cudaEventCreateWithFlags(&ev_join, cudaEventDisableTiming);
        cudaFuncSetAttribute(attnv_gemm_t, cudaFuncAttributeMaxDynamicSharedMemorySize,
                             AV_SMEM);
        cudaFuncSetAttribute(scores_gemm_t, cudaFuncAttributeMaxDynamicSharedMemorySize,
                             SC_SMEM);
    }

    // fork: cache shift overlaps all compute (nothing downstream reads shifted copy)
    cudaEventRecord(ev_fork, 0);
    cudaStreamWaitEvent(s_copy, ev_fork, 0);
    shift_caches<<<65280, 256, 0, s_copy>>>((const float4*)ck, (const float4*)cv,
                                            (float4*)out);
    cudaEventRecord(ev_join, s_copy);

    // compute chain on main stream, reading ORIGINAL caches
    qkv_gemm_t<<<dim3(48, QSPLIT), 256>>>(x, wq, wk, wv);
    rope_scatter<<<128, 256>>>(freqs, out);
    scores_gemm_t<<<dim3(32, 64), 256, SC_SMEM>>>(ck, mask);
    softmax_k<<<4096, 256>>>();
    attnv_gemm_t<<<dim3(64, 4), 256, AV_SMEM>>>(cv);
    attnv_reduce<<<512, 256>>>();
    out_gemm_t<<<dim3(32, OSPLIT), 256>>>(wo);
    out_reduce<<<512, 256>>>(out);

    // join: shift must complete before harness observes d_out
    cudaStreamWaitEvent(0, ev_join, 0);
}